// round 1
// baseline (speedup 1.0000x reference)
#include <cuda_runtime.h>
#include <math.h>

// Problem constants (fixed shapes for this problem)
#define HN 100000      // nodes per type
#define EN 200000      // edges per edge type
#define HDIM 128       // hidden
#define NHEAD 4
#define DHEAD 32

static const float INV_SQRT_D = 0.17677669529663687f; // 1/sqrt(32)

// ---------------- scratch layout (single big __device__ symbol) ----------------
constexpr size_t SN = (size_t)HN * HDIM;           // 12,800,000 floats per node buffer
constexpr size_t O_XS0 = 0;
constexpr size_t O_XS1 = SN;
constexpr size_t O_Q0  = 2*SN;
constexpr size_t O_Q1  = 3*SN;
constexpr size_t O_KT0 = 4*SN;
constexpr size_t O_KT1 = 5*SN;
constexpr size_t O_KT2 = 6*SN;
constexpr size_t O_VT0 = 7*SN;
constexpr size_t O_VT1 = 8*SN;
constexpr size_t O_VT2 = 9*SN;
constexpr size_t O_MSG0 = 10*SN;
constexpr size_t O_MSG1 = 11*SN;
constexpr size_t O_DEN0 = 12*SN;
constexpr size_t O_DEN1 = O_DEN0 + (size_t)HN*NHEAD;
constexpr size_t O_MX0  = O_DEN1 + (size_t)HN*NHEAD;
constexpr size_t O_MX1  = O_MX0  + (size_t)HN*NHEAD;
constexpr size_t O_SC0  = O_MX1  + (size_t)HN*NHEAD;
constexpr size_t O_SC1  = O_SC0 + (size_t)EN*NHEAD;
constexpr size_t O_SC2  = O_SC1 + (size_t)EN*NHEAD;
constexpr size_t O_WE   = O_SC2 + (size_t)EN*NHEAD;    // 12 matrices of 128*128
constexpr size_t O_BE   = O_WE + (size_t)12*HDIM*HDIM; // 12 vectors of 128
constexpr size_t SCRATCH_TOTAL = O_BE + (size_t)12*HDIM;

__device__ float g_scratch[SCRATCH_TOTAL];

// ---------------- helpers ----------------
__device__ __forceinline__ void atomicMaxFloat(float* addr, float v) {
    if (v >= 0.f) atomicMax((int*)addr, __float_as_int(v));
    else          atomicMin((unsigned int*)addr, __float_as_uint(v));
}

__device__ __forceinline__ float gelu_exact(float x) {
    return 0.5f * x * (1.0f + erff(x * 0.70710678118654752f));
}

// ---------------- composite relation weights ----------------
// WE[(l*3+r)*2+kv][i][h*32+e] = sum_d W{k|v}[l][src(r)][i][h*32+d] * {K|V}rel[l][r][h][d][e]
// bE analogous from bias.
__global__ void compose_kernel(const float* __restrict__ Wk, const float* __restrict__ bk,
                               const float* __restrict__ Wv, const float* __restrict__ bv,
                               const float* __restrict__ Krel, const float* __restrict__ Vrel,
                               float* __restrict__ WE, float* __restrict__ bE)
{
    int b = blockIdx.x;                 // 0..11
    int l = b / 6; int rem = b % 6;
    int kv = rem / 3; int r = rem % 3;
    int s = (r == 0) ? 0 : 1;           // ET = [(0,1),(1,0),(1,1)]
    const float* W  = (kv ? Wv : Wk) + (size_t)(l*2 + s) * HDIM * HDIM;
    const float* bb = (kv ? bv : bk) + (size_t)(l*2 + s) * HDIM;
    const float* R  = (kv ? Vrel : Krel) + (size_t)(l*3 + r) * NHEAD * DHEAD * DHEAD;
    float* WO = WE + (size_t)((l*3 + r)*2 + kv) * HDIM * HDIM;
    float* bO = bE + (size_t)((l*3 + r)*2 + kv) * HDIM;

    __shared__ float Rs[NHEAD*DHEAD*DHEAD];
    for (int i = threadIdx.x; i < NHEAD*DHEAD*DHEAD; i += blockDim.x) Rs[i] = R[i];
    __syncthreads();

    for (int o = threadIdx.x; o < HDIM*HDIM; o += blockDim.x) {
        int i = o >> 7; int j = o & 127;
        int h = j >> 5; int e = j & 31;
        float sum = 0.f;
        #pragma unroll
        for (int d = 0; d < DHEAD; d++)
            sum += W[i*HDIM + h*DHEAD + d] * Rs[(h*DHEAD + d)*DHEAD + e];
        WO[o] = sum;
    }
    if (threadIdx.x < HDIM) {
        int j = threadIdx.x; int h = j >> 5; int e = j & 31;
        float sum = 0.f;
        #pragma unroll
        for (int d = 0; d < DHEAD; d++)
            sum += bb[h*DHEAD + d] * Rs[(h*DHEAD + d)*DHEAD + e];
        bO[j] = sum;
    }
}

// ---------------- generic GEMM: C[n, 0..127] = post(pre(A[n,0..K-1]) @ B + bias) ----------------
// flags bit0: pre-gelu (A = gelu(A/den)), bit1: post skip-blend + relu (reads Cold)
__global__ void gemm_kernel(const float* __restrict__ A, const float* __restrict__ B,
                            const float* __restrict__ bias, float* __restrict__ C,
                            const float* __restrict__ Cold, const float* __restrict__ den,
                            const float* __restrict__ skipPtr,
                            int N, int K, int flags)
{
    extern __shared__ float sm[];
    float* Bs = sm;                 // K*128
    float* As = sm + (size_t)K*HDIM; // 64*K
    __shared__ float biass[HDIM];

    int tid = threadIdx.x;
    for (int i = tid; i < K*HDIM; i += 256) Bs[i] = B[i];
    if (tid < HDIM) biass[tid] = bias[tid];

    int row0 = blockIdx.x * 64;
    bool preGelu = flags & 1;
    for (int i = tid; i < 64*K; i += 256) {
        int r = i / K, c = i - r*K;
        int n = row0 + r;
        float a = 0.f;
        if (n < N) {
            a = A[(size_t)n*K + c];
            if (preGelu) {
                float d = den[(size_t)n*NHEAD + (c >> 5)];
                a = (d > 0.f) ? a / d : 0.f;
                a = gelu_exact(a);
            }
        }
        As[i] = a;
    }
    __syncthreads();

    int tx = tid & 31, ty = tid >> 5;
    float acc[8][4];
    #pragma unroll
    for (int r = 0; r < 8; r++) { acc[r][0]=0.f; acc[r][1]=0.f; acc[r][2]=0.f; acc[r][3]=0.f; }

    const float4* Bs4 = (const float4*)Bs;
    #pragma unroll 4
    for (int k = 0; k < K; k++) {
        float4 b = Bs4[k*32 + tx];
        #pragma unroll
        for (int r = 0; r < 8; r++) {
            float a = As[(ty*8 + r)*K + k];
            acc[r][0] += a*b.x; acc[r][1] += a*b.y; acc[r][2] += a*b.z; acc[r][3] += a*b.w;
        }
    }

    bool blend = flags & 2;
    float askip = 0.f;
    if (blend) askip = 1.f / (1.f + expf(-skipPtr[0]));

    #pragma unroll
    for (int r = 0; r < 8; r++) {
        int n = row0 + ty*8 + r;
        if (n >= N) break;
        float4 c;
        c.x = acc[r][0] + biass[tx*4+0];
        c.y = acc[r][1] + biass[tx*4+1];
        c.z = acc[r][2] + biass[tx*4+2];
        c.w = acc[r][3] + biass[tx*4+3];
        if (blend) {
            float4 old = *(const float4*)&Cold[(size_t)n*HDIM + tx*4];
            c.x = fmaxf(askip*c.x + (1.f-askip)*old.x, 0.f);
            c.y = fmaxf(askip*c.y + (1.f-askip)*old.y, 0.f);
            c.z = fmaxf(askip*c.z + (1.f-askip)*old.z, 0.f);
            c.w = fmaxf(askip*c.w + (1.f-askip)*old.w, 0.f);
        }
        *(float4*)&C[(size_t)n*HDIM + tx*4] = c;
    }
}

// ---------------- per-layer init: mx=-inf, den=0, msg=0 ----------------
__global__ void fill_kernel(float* __restrict__ mx0, float* __restrict__ mx1,
                            float* __restrict__ den0, float* __restrict__ den1,
                            float* __restrict__ msg0, float* __restrict__ msg1, int N)
{
    int i = blockIdx.x * blockDim.x + threadIdx.x;
    if (i < N*NHEAD) {
        mx0[i] = -INFINITY; mx1[i] = -INFINITY;
        den0[i] = 0.f; den1[i] = 0.f;
    }
    if (i < N*HDIM) { msg0[i] = 0.f; msg1[i] = 0.f; }
}

// ---------------- edge pass B: scores + running max ----------------
__global__ void edge_score_kernel(const int* __restrict__ edge, int E,
                                  const float* __restrict__ q, const float* __restrict__ kt,
                                  float* __restrict__ sc, float* __restrict__ mx,
                                  const float* __restrict__ prel)
{
    int g = blockIdx.x * blockDim.x + threadIdx.x;
    int w = g >> 5;
    if (w >= E) return;
    int lane = threadIdx.x & 31;
    int src = edge[w], dst = edge[E + w];
    int h = lane >> 3, sub = lane & 7;

    float4 qv = *(const float4*)&q[(size_t)dst*HDIM + h*DHEAD + sub*4];
    float4 kv = *(const float4*)&kt[(size_t)src*HDIM + h*DHEAD + sub*4];
    float s = qv.x*kv.x + qv.y*kv.y + qv.z*kv.z + qv.w*kv.w;
    s += __shfl_down_sync(0xffffffffu, s, 4);
    s += __shfl_down_sync(0xffffffffu, s, 2);
    s += __shfl_down_sync(0xffffffffu, s, 1);
    if (sub == 0) {
        s *= prel[h] * INV_SQRT_D;
        sc[(size_t)w*NHEAD + h] = s;
        atomicMaxFloat(&mx[(size_t)dst*NHEAD + h], s);
    }
}

// ---------------- edge pass C: exp, denominator, weighted value scatter ----------------
__global__ void edge_accum_kernel(const int* __restrict__ edge, int E,
                                  const float* __restrict__ vt, const float* __restrict__ sc,
                                  const float* __restrict__ mx,
                                  float* __restrict__ den, float* __restrict__ msg)
{
    int g = blockIdx.x * blockDim.x + threadIdx.x;
    int w = g >> 5;
    if (w >= E) return;
    int lane = threadIdx.x & 31;
    int src = edge[w], dst = edge[E + w];
    int h = lane >> 3, sub = lane & 7;

    float s = sc[(size_t)w*NHEAD + h];
    float m = mx[(size_t)dst*NHEAD + h];
    float e = expf(s - m);
    if (sub == 0) atomicAdd(&den[(size_t)dst*NHEAD + h], e);

    float4 v = *(const float4*)&vt[(size_t)src*HDIM + h*DHEAD + sub*4];
    float* mp = &msg[(size_t)dst*HDIM + h*DHEAD + sub*4];
    atomicAdd(mp + 0, e * v.x);
    atomicAdd(mp + 1, e * v.y);
    atomicAdd(mp + 2, e * v.z);
    atomicAdd(mp + 3, e * v.w);
}

// ---------------- host orchestration ----------------
extern "C" void kernel_launch(void* const* d_in, const int* in_sizes, int n_in,
                              void* d_out, int out_size)
{
    const float* x_region = (const float*)d_in[0];
    const float* x_site   = (const float*)d_in[1];
    const float* pWr = (const float*)d_in[2];
    const float* pbr = (const float*)d_in[3];
    const float* pWs = (const float*)d_in[4];
    const float* pbs = (const float*)d_in[5];
    const float* Wk  = (const float*)d_in[6];
    const float* bk  = (const float*)d_in[7];
    const float* Wq  = (const float*)d_in[8];
    const float* bq  = (const float*)d_in[9];
    const float* Wv  = (const float*)d_in[10];
    const float* bv  = (const float*)d_in[11];
    const float* Wo  = (const float*)d_in[12];
    const float* bo  = (const float*)d_in[13];
    const float* skip = (const float*)d_in[14];
    const float* Krel = (const float*)d_in[15];
    const float* Vrel = (const float*)d_in[16];
    const float* prel = (const float*)d_in[17];
    const int* edges[3] = { (const int*)d_in[18], (const int*)d_in[19], (const int*)d_in[20] };

    int N = in_sizes[0] / 64;
    int E = in_sizes[18] / 2;

    float* base = nullptr;
    cudaGetSymbolAddress((void**)&base, g_scratch);

    float* xs[2]  = { base + O_XS0,  base + O_XS1 };
    float* qb[2]  = { base + O_Q0,   base + O_Q1 };
    float* ktb[3] = { base + O_KT0,  base + O_KT1, base + O_KT2 };
    float* vtb[3] = { base + O_VT0,  base + O_VT1, base + O_VT2 };
    float* msg[2] = { base + O_MSG0, base + O_MSG1 };
    float* den[2] = { base + O_DEN0, base + O_DEN1 };
    float* mx[2]  = { base + O_MX0,  base + O_MX1 };
    float* scb[3] = { base + O_SC0,  base + O_SC1, base + O_SC2 };
    float* WE = base + O_WE;
    float* bE = base + O_BE;

    const int srcType[3] = {0, 1, 1};
    const int dstType[3] = {1, 0, 1};

    // allow >48KB dynamic smem for the GEMM kernel (idempotent)
    cudaFuncSetAttribute(gemm_kernel, cudaFuncAttributeMaxDynamicSharedMemorySize, 128*768 + 1024);

    int gemmGrid = (N + 63) / 64;
    int edgeGrid = (E*32 + 255) / 256;
    int fillGrid = (N*HDIM + 255) / 256;

    // 0) composite relation weights (12 matrices)
    compose_kernel<<<12, 256>>>(Wk, bk, Wv, bv, Krel, Vrel, WE, bE);

    // 1) input projections
    gemm_kernel<<<gemmGrid, 256, 64*768>>>(x_region, pWr, pbr, xs[0], nullptr, nullptr, nullptr, N, 64, 0);
    gemm_kernel<<<gemmGrid, 256, 32*768>>>(x_site,   pWs, pbs, xs[1], nullptr, nullptr, nullptr, N, 32, 0);

    const int L = 2;
    for (int l = 0; l < L; l++) {
        fill_kernel<<<fillGrid, 256>>>(mx[0], mx[1], den[0], den[1], msg[0], msg[1], N);

        // q for both node types
        for (int t = 0; t < 2; t++) {
            gemm_kernel<<<gemmGrid, 256, 128*768>>>(xs[t], Wq + (size_t)(l*2+t)*HDIM*HDIM,
                                                    bq + (size_t)(l*2+t)*HDIM, qb[t],
                                                    nullptr, nullptr, nullptr, N, 128, 0);
        }
        // kt / vt via composite weights, per edge type
        for (int r = 0; r < 3; r++) {
            int s = srcType[r];
            const float* WEk = WE + (size_t)((l*3+r)*2 + 0)*HDIM*HDIM;
            const float* bEk = bE + (size_t)((l*3+r)*2 + 0)*HDIM;
            const float* WEv = WE + (size_t)((l*3+r)*2 + 1)*HDIM*HDIM;
            const float* bEv = bE + (size_t)((l*3+r)*2 + 1)*HDIM;
            gemm_kernel<<<gemmGrid, 256, 128*768>>>(xs[s], WEk, bEk, ktb[r], nullptr, nullptr, nullptr, N, 128, 0);
            gemm_kernel<<<gemmGrid, 256, 128*768>>>(xs[s], WEv, bEv, vtb[r], nullptr, nullptr, nullptr, N, 128, 0);
        }
        // edge scores + max
        for (int r = 0; r < 3; r++) {
            int d = dstType[r];
            edge_score_kernel<<<edgeGrid, 256>>>(edges[r], E, qb[d], ktb[r], scb[r], mx[d],
                                                 prel + (size_t)(l*3+r)*NHEAD);
        }
        // edge exp/denominator/scatter
        for (int r = 0; r < 3; r++) {
            int d = dstType[r];
            edge_accum_kernel<<<edgeGrid, 256>>>(edges[r], E, vtb[r], scb[r], mx[d], den[d], msg[d]);
        }
        // finalize: out = relu(a*(gelu(msg/den)@Wo + bo) + (1-a)*xs)
        for (int t = 0; t < 2; t++) {
            float* Cptr = (l == L-1) ? ((float*)d_out + (size_t)t*N*HDIM) : xs[t];
            gemm_kernel<<<gemmGrid, 256, 128*768>>>(msg[t], Wo + (size_t)(l*2+t)*HDIM*HDIM,
                                                    bo + (size_t)(l*2+t)*HDIM, Cptr,
                                                    xs[t], den[t], skip + l*2 + t, N, 128, 3);
        }
    }
}

// round 2
// speedup vs baseline: 1.1988x; 1.1988x over previous
#include <cuda_runtime.h>
#include <math.h>
#include <stdint.h>

// Problem constants (fixed shapes for this problem)
#define HN 100000      // nodes per type
#define EN 200000      // edges per edge type
#define HDIM 128       // hidden
#define NHEAD 4
#define DHEAD 32

static const float INV_SQRT_D = 0.17677669529663687f; // 1/sqrt(32)

// ---------------- scratch layout (single big __device__ symbol) ----------------
constexpr size_t SN = (size_t)HN * HDIM;
constexpr size_t O_XS0 = 0;
constexpr size_t O_XS1 = SN;
constexpr size_t O_Q0  = 2*SN;
constexpr size_t O_Q1  = 3*SN;
constexpr size_t O_KT0 = 4*SN;
constexpr size_t O_KT1 = 5*SN;
constexpr size_t O_KT2 = 6*SN;
constexpr size_t O_VT0 = 7*SN;
constexpr size_t O_VT1 = 8*SN;
constexpr size_t O_VT2 = 9*SN;
constexpr size_t O_MSG0 = 10*SN;
constexpr size_t O_MSG1 = 11*SN;
constexpr size_t O_DEN0 = 12*SN;
constexpr size_t O_DEN1 = O_DEN0 + (size_t)HN*NHEAD;
constexpr size_t O_MX0  = O_DEN1 + (size_t)HN*NHEAD;
constexpr size_t O_MX1  = O_MX0  + (size_t)HN*NHEAD;
constexpr size_t O_SC0  = O_MX1  + (size_t)HN*NHEAD;
constexpr size_t O_SC1  = O_SC0 + (size_t)EN*NHEAD;
constexpr size_t O_SC2  = O_SC1 + (size_t)EN*NHEAD;
constexpr size_t O_WE   = O_SC2 + (size_t)EN*NHEAD;
constexpr size_t O_BE   = O_WE + (size_t)12*HDIM*HDIM;
constexpr size_t SCRATCH_TOTAL = O_BE + (size_t)12*HDIM;

__device__ float g_scratch[SCRATCH_TOTAL];

// ---------------- helpers ----------------
__device__ __forceinline__ void atomicMaxFloat(float* addr, float v) {
    if (v >= 0.f) atomicMax((int*)addr, __float_as_int(v));
    else          atomicMin((unsigned int*)addr, __float_as_uint(v));
}

__device__ __forceinline__ float gelu_exact(float x) {
    return 0.5f * x * (1.0f + erff(x * 0.70710678118654752f));
}

__device__ __forceinline__ uint32_t f2tf32(float x) {
    uint32_t u;
    asm("cvt.rna.tf32.f32 %0, %1;" : "=r"(u) : "f"(x));
    return u;
}

__device__ __forceinline__ void mma_tf32(float c[4], const uint32_t a[4], const uint32_t b[2]) {
    asm volatile(
        "mma.sync.aligned.m16n8k8.row.col.f32.tf32.tf32.f32 "
        "{%0,%1,%2,%3}, {%4,%5,%6,%7}, {%8,%9}, {%0,%1,%2,%3};"
        : "+f"(c[0]), "+f"(c[1]), "+f"(c[2]), "+f"(c[3])
        : "r"(a[0]), "r"(a[1]), "r"(a[2]), "r"(a[3]), "r"(b[0]), "r"(b[1]));
}

// ---------------- composite relation weights ----------------
__global__ void compose_kernel(const float* __restrict__ Wk, const float* __restrict__ bk,
                               const float* __restrict__ Wv, const float* __restrict__ bv,
                               const float* __restrict__ Krel, const float* __restrict__ Vrel,
                               float* __restrict__ WE, float* __restrict__ bE)
{
    int b = blockIdx.x;                 // 0..11
    int l = b / 6; int rem = b % 6;
    int kv = rem / 3; int r = rem % 3;
    int s = (r == 0) ? 0 : 1;           // ET = [(0,1),(1,0),(1,1)]
    const float* W  = (kv ? Wv : Wk) + (size_t)(l*2 + s) * HDIM * HDIM;
    const float* bb = (kv ? bv : bk) + (size_t)(l*2 + s) * HDIM;
    const float* R  = (kv ? Vrel : Krel) + (size_t)(l*3 + r) * NHEAD * DHEAD * DHEAD;
    float* WO = WE + (size_t)((l*3 + r)*2 + kv) * HDIM * HDIM;
    float* bO = bE + (size_t)((l*3 + r)*2 + kv) * HDIM;

    __shared__ float Rs[NHEAD*DHEAD*DHEAD];
    for (int i = threadIdx.x; i < NHEAD*DHEAD*DHEAD; i += blockDim.x) Rs[i] = R[i];
    __syncthreads();

    for (int o = threadIdx.x; o < HDIM*HDIM; o += blockDim.x) {
        int i = o >> 7; int j = o & 127;
        int h = j >> 5; int e = j & 31;
        float sum = 0.f;
        #pragma unroll
        for (int d = 0; d < DHEAD; d++)
            sum += W[i*HDIM + h*DHEAD + d] * Rs[(h*DHEAD + d)*DHEAD + e];
        WO[o] = sum;
    }
    if (threadIdx.x < HDIM) {
        int j = threadIdx.x; int h = j >> 5; int e = j & 31;
        float sum = 0.f;
        #pragma unroll
        for (int d = 0; d < DHEAD; d++)
            sum += bb[h*DHEAD + d] * Rs[(h*DHEAD + d)*DHEAD + e];
        bO[j] = sum;
    }
}

// ---------------- tf32 tensor-core GEMM ----------------
// C[n, 0..127] = post(pre(A[n,0..K-1]) @ B[K,128] + bias)
// flags bit0: pre-gelu (A = gelu(A/den)), bit1: post skip-blend + relu (reads Cold)
template<int K>
__global__ __launch_bounds__(256) void mma_gemm(
        const float* __restrict__ A, const float* __restrict__ B,
        const float* __restrict__ bias, float* __restrict__ C,
        const float* __restrict__ Cold, const float* __restrict__ den,
        const float* __restrict__ skipPtr, int N, int flags)
{
    constexpr int KP = K + 4;           // padded A row
    constexpr int K4 = K / 4;
    extern __shared__ uint32_t smu[];
    uint32_t* As = smu;                  // 128 * KP
    uint32_t* Bs = smu + 128*KP;         // K * 132
    float* biass = (float*)(Bs + K*132); // 128

    int tid = threadIdx.x;
    int row0 = blockIdx.x * 128;
    bool preGelu = flags & 1;

    if (tid < 128) biass[tid] = bias[tid];

    // load B [K][128] -> tf32, pad to 132
    const float4* B4 = (const float4*)B;
    for (int i = tid; i < K*32; i += 256) {
        int k = i >> 5, c4 = i & 31;
        float4 v = B4[i];
        uint32_t* dst = &Bs[k*132 + c4*4];
        dst[0] = f2tf32(v.x); dst[1] = f2tf32(v.y);
        dst[2] = f2tf32(v.z); dst[3] = f2tf32(v.w);
    }

    // load A tile [128][K] -> tf32, with optional pre-gelu(softmax-normalize)
    for (int i = tid; i < 128*K4; i += 256) {
        int r = i / K4, c4 = i % K4;
        int n = row0 + r;
        float4 v = make_float4(0.f, 0.f, 0.f, 0.f);
        if (n < N) {
            v = ((const float4*)A)[(size_t)n*K4 + c4];
            if (preGelu) {
                float d = den[(size_t)n*NHEAD + (c4 >> 3)];
                float inv = (d > 0.f) ? 1.f/d : 0.f;
                v.x = gelu_exact(v.x*inv); v.y = gelu_exact(v.y*inv);
                v.z = gelu_exact(v.z*inv); v.w = gelu_exact(v.w*inv);
            }
        }
        uint32_t* dst = &As[r*KP + c4*4];
        dst[0] = f2tf32(v.x); dst[1] = f2tf32(v.y);
        dst[2] = f2tf32(v.z); dst[3] = f2tf32(v.w);
    }
    __syncthreads();

    int lane = tid & 31, w = tid >> 5;
    int wm = (w & 1) * 64;        // 2 m-blocks of 64
    int wn = (w >> 1) * 32;       // 4 n-blocks of 32
    int lg = lane >> 2;           // group id 0..7
    int lt = lane & 3;            // thread-in-group 0..3

    float acc[4][4][4];
    #pragma unroll
    for (int mt = 0; mt < 4; mt++)
        #pragma unroll
        for (int nt = 0; nt < 4; nt++)
            #pragma unroll
            for (int j = 0; j < 4; j++) acc[mt][nt][j] = 0.f;

    #pragma unroll 2
    for (int k0 = 0; k0 < K; k0 += 8) {
        uint32_t af[4][4];
        #pragma unroll
        for (int mt = 0; mt < 4; mt++) {
            int r = wm + mt*16 + lg;
            af[mt][0] = As[r*KP + k0 + lt];
            af[mt][1] = As[(r+8)*KP + k0 + lt];
            af[mt][2] = As[r*KP + k0 + lt + 4];
            af[mt][3] = As[(r+8)*KP + k0 + lt + 4];
        }
        uint32_t bf[4][2];
        #pragma unroll
        for (int nt = 0; nt < 4; nt++) {
            bf[nt][0] = Bs[(k0 + lt)*132 + wn + nt*8 + lg];
            bf[nt][1] = Bs[(k0 + lt + 4)*132 + wn + nt*8 + lg];
        }
        #pragma unroll
        for (int mt = 0; mt < 4; mt++)
            #pragma unroll
            for (int nt = 0; nt < 4; nt++)
                mma_tf32(acc[mt][nt], af[mt], bf[nt]);
    }

    bool blend = flags & 2;
    float askip = 0.f;
    if (blend) askip = 1.f / (1.f + expf(-skipPtr[0]));

    #pragma unroll
    for (int mt = 0; mt < 4; mt++) {
        #pragma unroll
        for (int nt = 0; nt < 4; nt++) {
            int col = wn + nt*8 + lt*2;
            float b0 = biass[col], b1 = biass[col+1];
            #pragma unroll
            for (int half = 0; half < 2; half++) {
                int r = row0 + wm + mt*16 + lg + half*8;
                if (r >= N) continue;
                float2 o;
                o.x = acc[mt][nt][half*2 + 0] + b0;
                o.y = acc[mt][nt][half*2 + 1] + b1;
                if (blend) {
                    float2 old = *(const float2*)&Cold[(size_t)r*HDIM + col];
                    o.x = fmaxf(askip*o.x + (1.f-askip)*old.x, 0.f);
                    o.y = fmaxf(askip*o.y + (1.f-askip)*old.y, 0.f);
                }
                *(float2*)&C[(size_t)r*HDIM + col] = o;
            }
        }
    }
}

// ---------------- per-layer init: mx=-inf, den=0, msg=0 ----------------
__global__ void fill_kernel(float* __restrict__ mx0, float* __restrict__ mx1,
                            float* __restrict__ den0, float* __restrict__ den1,
                            float* __restrict__ msg0, float* __restrict__ msg1, int N)
{
    int i = blockIdx.x * blockDim.x + threadIdx.x;
    if (i < N*NHEAD) {
        mx0[i] = -INFINITY; mx1[i] = -INFINITY;
        den0[i] = 0.f; den1[i] = 0.f;
    }
    if (i < N*HDIM) { msg0[i] = 0.f; msg1[i] = 0.f; }
}

// ---------------- edge pass B: scores + running max ----------------
__global__ void edge_score_kernel(const int* __restrict__ edge, int E,
                                  const float* __restrict__ q, const float* __restrict__ kt,
                                  float* __restrict__ sc, float* __restrict__ mx,
                                  const float* __restrict__ prel)
{
    int g = blockIdx.x * blockDim.x + threadIdx.x;
    int w = g >> 5;
    if (w >= E) return;
    int lane = threadIdx.x & 31;
    int src = edge[w], dst = edge[E + w];
    int h = lane >> 3, sub = lane & 7;

    float4 qv = *(const float4*)&q[(size_t)dst*HDIM + h*DHEAD + sub*4];
    float4 kv = *(const float4*)&kt[(size_t)src*HDIM + h*DHEAD + sub*4];
    float s = qv.x*kv.x + qv.y*kv.y + qv.z*kv.z + qv.w*kv.w;
    s += __shfl_down_sync(0xffffffffu, s, 4);
    s += __shfl_down_sync(0xffffffffu, s, 2);
    s += __shfl_down_sync(0xffffffffu, s, 1);
    if (sub == 0) {
        s *= prel[h] * INV_SQRT_D;
        sc[(size_t)w*NHEAD + h] = s;
        atomicMaxFloat(&mx[(size_t)dst*NHEAD + h], s);
    }
}

// ---------------- edge pass C: exp, denominator, weighted value scatter ----------------
__global__ void edge_accum_kernel(const int* __restrict__ edge, int E,
                                  const float* __restrict__ vt, const float* __restrict__ sc,
                                  const float* __restrict__ mx,
                                  float* __restrict__ den, float* __restrict__ msg)
{
    int g = blockIdx.x * blockDim.x + threadIdx.x;
    int w = g >> 5;
    if (w >= E) return;
    int lane = threadIdx.x & 31;
    int src = edge[w], dst = edge[E + w];
    int h = lane >> 3, sub = lane & 7;

    float s = sc[(size_t)w*NHEAD + h];
    float m = mx[(size_t)dst*NHEAD + h];
    float e = expf(s - m);
    if (sub == 0) atomicAdd(&den[(size_t)dst*NHEAD + h], e);

    float4 v = *(const float4*)&vt[(size_t)src*HDIM + h*DHEAD + sub*4];
    float* mp = &msg[(size_t)dst*HDIM + h*DHEAD + sub*4];
    atomicAdd(mp + 0, e * v.x);
    atomicAdd(mp + 1, e * v.y);
    atomicAdd(mp + 2, e * v.z);
    atomicAdd(mp + 3, e * v.w);
}

// ---------------- host orchestration ----------------
extern "C" void kernel_launch(void* const* d_in, const int* in_sizes, int n_in,
                              void* d_out, int out_size)
{
    const float* x_region = (const float*)d_in[0];
    const float* x_site   = (const float*)d_in[1];
    const float* pWr = (const float*)d_in[2];
    const float* pbr = (const float*)d_in[3];
    const float* pWs = (const float*)d_in[4];
    const float* pbs = (const float*)d_in[5];
    const float* Wk  = (const float*)d_in[6];
    const float* bk  = (const float*)d_in[7];
    const float* Wq  = (const float*)d_in[8];
    const float* bq  = (const float*)d_in[9];
    const float* Wv  = (const float*)d_in[10];
    const float* bv  = (const float*)d_in[11];
    const float* Wo  = (const float*)d_in[12];
    const float* bo  = (const float*)d_in[13];
    const float* skip = (const float*)d_in[14];
    const float* Krel = (const float*)d_in[15];
    const float* Vrel = (const float*)d_in[16];
    const float* prel = (const float*)d_in[17];
    const int* edges[3] = { (const int*)d_in[18], (const int*)d_in[19], (const int*)d_in[20] };

    int N = in_sizes[0] / 64;
    int E = in_sizes[18] / 2;

    float* base = nullptr;
    cudaGetSymbolAddress((void**)&base, g_scratch);

    float* xs[2]  = { base + O_XS0,  base + O_XS1 };
    float* qb[2]  = { base + O_Q0,   base + O_Q1 };
    float* ktb[3] = { base + O_KT0,  base + O_KT1, base + O_KT2 };
    float* vtb[3] = { base + O_VT0,  base + O_VT1, base + O_VT2 };
    float* msg[2] = { base + O_MSG0, base + O_MSG1 };
    float* den[2] = { base + O_DEN0, base + O_DEN1 };
    float* mx[2]  = { base + O_MX0,  base + O_MX1 };
    float* scb[3] = { base + O_SC0,  base + O_SC1, base + O_SC2 };
    float* WE = base + O_WE;
    float* bE = base + O_BE;

    const int srcType[3] = {0, 1, 1};
    const int dstType[3] = {1, 0, 1};

    // dynamic smem sizes (bytes): As 128*(K+4) + Bs K*132 + bias 128, all 4B words
    const int SM128 = (128*132 + 128*132 + 128) * 4;  // 135680
    const int SM64  = (128*68  + 64*132  + 128) * 4;  // 69120
    const int SM32  = (128*36  + 32*132  + 128) * 4;  // 35840
    cudaFuncSetAttribute(mma_gemm<128>, cudaFuncAttributeMaxDynamicSharedMemorySize, SM128);
    cudaFuncSetAttribute(mma_gemm<64>,  cudaFuncAttributeMaxDynamicSharedMemorySize, SM64);
    cudaFuncSetAttribute(mma_gemm<32>,  cudaFuncAttributeMaxDynamicSharedMemorySize, SM32);

    int gemmGrid = (N + 127) / 128;
    int edgeGrid = (E*32 + 255) / 256;
    int fillGrid = (N*HDIM + 255) / 256;

    // 0) composite relation weights (12 matrices)
    compose_kernel<<<12, 256>>>(Wk, bk, Wv, bv, Krel, Vrel, WE, bE);

    // 1) input projections
    mma_gemm<64><<<gemmGrid, 256, SM64>>>(x_region, pWr, pbr, xs[0], nullptr, nullptr, nullptr, N, 0);
    mma_gemm<32><<<gemmGrid, 256, SM32>>>(x_site,   pWs, pbs, xs[1], nullptr, nullptr, nullptr, N, 0);

    const int L = 2;
    for (int l = 0; l < L; l++) {
        fill_kernel<<<fillGrid, 256>>>(mx[0], mx[1], den[0], den[1], msg[0], msg[1], N);

        // q for both node types
        for (int t = 0; t < 2; t++) {
            mma_gemm<128><<<gemmGrid, 256, SM128>>>(xs[t], Wq + (size_t)(l*2+t)*HDIM*HDIM,
                                                    bq + (size_t)(l*2+t)*HDIM, qb[t],
                                                    nullptr, nullptr, nullptr, N, 0);
        }
        // kt / vt via composite weights, per edge type
        for (int r = 0; r < 3; r++) {
            int s = srcType[r];
            const float* WEk = WE + (size_t)((l*3+r)*2 + 0)*HDIM*HDIM;
            const float* bEk = bE + (size_t)((l*3+r)*2 + 0)*HDIM;
            const float* WEv = WE + (size_t)((l*3+r)*2 + 1)*HDIM*HDIM;
            const float* bEv = bE + (size_t)((l*3+r)*2 + 1)*HDIM;
            mma_gemm<128><<<gemmGrid, 256, SM128>>>(xs[s], WEk, bEk, ktb[r], nullptr, nullptr, nullptr, N, 0);
            mma_gemm<128><<<gemmGrid, 256, SM128>>>(xs[s], WEv, bEv, vtb[r], nullptr, nullptr, nullptr, N, 0);
        }
        // edge scores + max
        for (int r = 0; r < 3; r++) {
            int d = dstType[r];
            edge_score_kernel<<<edgeGrid, 256>>>(edges[r], E, qb[d], ktb[r], scb[r], mx[d],
                                                 prel + (size_t)(l*3+r)*NHEAD);
        }
        // edge exp/denominator/scatter
        for (int r = 0; r < 3; r++) {
            int d = dstType[r];
            edge_accum_kernel<<<edgeGrid, 256>>>(edges[r], E, vtb[r], scb[r], mx[d], den[d], msg[d]);
        }
        // finalize: out = relu(a*(gelu(msg/den)@Wo + bo) + (1-a)*xs)
        for (int t = 0; t < 2; t++) {
            float* Cptr = (l == L-1) ? ((float*)d_out + (size_t)t*N*HDIM) : xs[t];
            mma_gemm<128><<<gemmGrid, 256, SM128>>>(msg[t], Wo + (size_t)(l*2+t)*HDIM*HDIM,
                                                    bo + (size_t)(l*2+t)*HDIM, Cptr,
                                                    xs[t], den[t], skip + l*2 + t, N, 3);
        }
    }
}

// round 6
// speedup vs baseline: 1.9107x; 1.5938x over previous
#include <cuda_runtime.h>
#include <math.h>
#include <stdint.h>

// Problem constants (fixed shapes for this problem)
#define HN 100000      // nodes per type
#define EN 200000      // edges per edge type
#define HDIM 128       // hidden
#define NHEAD 4
#define DHEAD 32

static const float INV_SQRT_D = 0.17677669529663687f; // 1/sqrt(32)

// ---------------- scratch layout ----------------
constexpr size_t SN = (size_t)HN * HDIM;     // one [N,128] buffer
constexpr size_t O_XS0   = 0;
constexpr size_t O_XS1   = SN;
constexpr size_t O_Q0    = 2*SN;
constexpr size_t O_Q1    = 3*SN;
constexpr size_t O_KTVT0 = 4*SN;             // [N,256] kt|vt for edge type 0
constexpr size_t O_KTVT1 = 6*SN;
constexpr size_t O_KTVT2 = 8*SN;
constexpr size_t O_MSG0  = 10*SN;
constexpr size_t O_MSG1  = 11*SN;
constexpr size_t O_DEN0  = 12*SN;
constexpr size_t O_DEN1  = O_DEN0 + (size_t)HN*NHEAD;
constexpr size_t O_PW    = O_DEN1 + (size_t)HN*NHEAD;   // 2 layers * 8 chunks * 128*128
constexpr size_t O_PB    = O_PW + (size_t)16*HDIM*HDIM; // 16 * 128
constexpr size_t SCRATCH_TOTAL = O_PB + (size_t)16*HDIM;

__device__ float g_scratch[SCRATCH_TOTAL];

// ---------------- helpers ----------------
__device__ __forceinline__ float gelu_exact(float x) {
    return 0.5f * x * (1.0f + erff(x * 0.70710678118654752f));
}

__device__ __forceinline__ uint32_t f2tf32(float x) {
    uint32_t u;
    asm("cvt.rna.tf32.f32 %0, %1;" : "=r"(u) : "f"(x));
    return u;
}

__device__ __forceinline__ void mma_tf32(float c[4], const uint32_t a[4], const uint32_t b[2]) {
    asm volatile(
        "mma.sync.aligned.m16n8k8.row.col.f32.tf32.tf32.f32 "
        "{%0,%1,%2,%3}, {%4,%5,%6,%7}, {%8,%9}, {%0,%1,%2,%3};"
        : "+f"(c[0]), "+f"(c[1]), "+f"(c[2]), "+f"(c[3])
        : "r"(a[0]), "r"(a[1]), "r"(a[2]), "r"(a[3]), "r"(b[0]), "r"(b[1]));
}

// ---------------- pack kernel: packed weight chunks per (layer, node type) ----------------
// Chunk map per layer (8 chunks of 128x128):
//   c0: Wq[l][0]                   (type 0)
//   c1: Wk[l][0] o Krel[l][0]      (type 0, edge r0: src=0)
//   c2: Wv[l][0] o Vrel[l][0]
//   c3: Wq[l][1]                   (type 1)
//   c4: Wk[l][1] o Krel[l][1]      (edge r1: src=1)
//   c5: Wv[l][1] o Vrel[l][1]
//   c6: Wk[l][1] o Krel[l][2]      (edge r2: src=1)
//   c7: Wv[l][1] o Vrel[l][2]
__global__ void pack_kernel(const float* __restrict__ Wq, const float* __restrict__ bq,
                            const float* __restrict__ Wk, const float* __restrict__ bk,
                            const float* __restrict__ Wv, const float* __restrict__ bv,
                            const float* __restrict__ Krel, const float* __restrict__ Vrel,
                            float* __restrict__ PW, float* __restrict__ PB)
{
    int b = blockIdx.x;     // 0..15
    int l = b >> 3, c = b & 7;
    float* WO = PW + (size_t)b * HDIM * HDIM;
    float* bO = PB + (size_t)b * HDIM;

    if (c == 0 || c == 3) {
        int t = (c == 3);
        const float* W = Wq + (size_t)(l*2 + t) * HDIM * HDIM;
        const float* bb = bq + (size_t)(l*2 + t) * HDIM;
        for (int i = threadIdx.x; i < HDIM*HDIM; i += blockDim.x) WO[i] = W[i];
        if (threadIdx.x < HDIM) bO[threadIdx.x] = bb[threadIdx.x];
        return;
    }

    // composite chunks
    int kv, r, s;
    if (c == 1) { kv = 0; r = 0; s = 0; }
    else if (c == 2) { kv = 1; r = 0; s = 0; }
    else if (c == 4) { kv = 0; r = 1; s = 1; }
    else if (c == 5) { kv = 1; r = 1; s = 1; }
    else if (c == 6) { kv = 0; r = 2; s = 1; }
    else { kv = 1; r = 2; s = 1; }

    const float* W  = (kv ? Wv : Wk) + (size_t)(l*2 + s) * HDIM * HDIM;
    const float* bb = (kv ? bv : bk) + (size_t)(l*2 + s) * HDIM;
    const float* R  = (kv ? Vrel : Krel) + (size_t)(l*3 + r) * NHEAD * DHEAD * DHEAD;

    __shared__ float Rs[NHEAD*DHEAD*DHEAD];
    for (int i = threadIdx.x; i < NHEAD*DHEAD*DHEAD; i += blockDim.x) Rs[i] = R[i];
    __syncthreads();

    for (int o = threadIdx.x; o < HDIM*HDIM; o += blockDim.x) {
        int i = o >> 7, j = o & 127;
        int h = j >> 5, e = j & 31;
        float sum = 0.f;
        #pragma unroll
        for (int d = 0; d < DHEAD; d++)
            sum += W[i*HDIM + h*DHEAD + d] * Rs[(h*DHEAD + d)*DHEAD + e];
        WO[o] = sum;
    }
    if (threadIdx.x < HDIM) {
        int j = threadIdx.x, h = j >> 5, e = j & 31;
        float sum = 0.f;
        #pragma unroll
        for (int d = 0; d < DHEAD; d++)
            sum += bb[h*DHEAD + d] * Rs[(h*DHEAD + d)*DHEAD + e];
        bO[j] = sum;
    }
}

// ---------------- single-output tf32 GEMM (input proj + finalize) ----------------
// flags bit0: pre-gelu (A = gelu(A/den)), bit1: post skip-blend + relu (reads Cold)
template<int K>
__global__ __launch_bounds__(256) void mma_gemm(
        const float* __restrict__ A, const float* __restrict__ B,
        const float* __restrict__ bias, float* __restrict__ C,
        const float* __restrict__ Cold, const float* __restrict__ den,
        const float* __restrict__ skipPtr, int N, int flags)
{
    constexpr int KP = K + 4;
    constexpr int K4 = K / 4;
    extern __shared__ uint32_t smu[];
    uint32_t* As = smu;                  // 128 * KP
    uint32_t* Bs = smu + 128*KP;         // K * 132
    float* biass = (float*)(Bs + K*132); // 128

    int tid = threadIdx.x;
    int row0 = blockIdx.x * 128;
    bool preGelu = flags & 1;

    if (tid < 128) biass[tid] = bias[tid];

    const float4* B4 = (const float4*)B;
    for (int i = tid; i < K*32; i += 256) {
        int k = i >> 5, c4 = i & 31;
        float4 v = B4[i];
        uint32_t* dst = &Bs[k*132 + c4*4];
        dst[0] = f2tf32(v.x); dst[1] = f2tf32(v.y);
        dst[2] = f2tf32(v.z); dst[3] = f2tf32(v.w);
    }

    for (int i = tid; i < 128*K4; i += 256) {
        int r = i / K4, c4 = i % K4;
        int n = row0 + r;
        float4 v = make_float4(0.f, 0.f, 0.f, 0.f);
        if (n < N) {
            v = ((const float4*)A)[(size_t)n*K4 + c4];
            if (preGelu) {
                float d = den[(size_t)n*NHEAD + (c4 >> 3)];
                float inv = (d > 0.f) ? 1.f/d : 0.f;
                v.x = gelu_exact(v.x*inv); v.y = gelu_exact(v.y*inv);
                v.z = gelu_exact(v.z*inv); v.w = gelu_exact(v.w*inv);
            }
        }
        uint32_t* dst = &As[r*KP + c4*4];
        dst[0] = f2tf32(v.x); dst[1] = f2tf32(v.y);
        dst[2] = f2tf32(v.z); dst[3] = f2tf32(v.w);
    }
    __syncthreads();

    int lane = tid & 31, w = tid >> 5;
    int wm = (w & 1) * 64;
    int wn = (w >> 1) * 32;
    int lg = lane >> 2;
    int lt = lane & 3;

    float acc[4][4][4];
    #pragma unroll
    for (int mt = 0; mt < 4; mt++)
        #pragma unroll
        for (int nt = 0; nt < 4; nt++)
            #pragma unroll
            for (int j = 0; j < 4; j++) acc[mt][nt][j] = 0.f;

    #pragma unroll 2
    for (int k0 = 0; k0 < K; k0 += 8) {
        uint32_t af[4][4];
        #pragma unroll
        for (int mt = 0; mt < 4; mt++) {
            int r = wm + mt*16 + lg;
            af[mt][0] = As[r*KP + k0 + lt];
            af[mt][1] = As[(r+8)*KP + k0 + lt];
            af[mt][2] = As[r*KP + k0 + lt + 4];
            af[mt][3] = As[(r+8)*KP + k0 + lt + 4];
        }
        uint32_t bf[4][2];
        #pragma unroll
        for (int nt = 0; nt < 4; nt++) {
            bf[nt][0] = Bs[(k0 + lt)*132 + wn + nt*8 + lg];
            bf[nt][1] = Bs[(k0 + lt + 4)*132 + wn + nt*8 + lg];
        }
        #pragma unroll
        for (int mt = 0; mt < 4; mt++)
            #pragma unroll
            for (int nt = 0; nt < 4; nt++)
                mma_tf32(acc[mt][nt], af[mt], bf[nt]);
    }

    bool blend = flags & 2;
    float askip = 0.f;
    if (blend) askip = 1.f / (1.f + expf(-skipPtr[0]));

    #pragma unroll
    for (int mt = 0; mt < 4; mt++) {
        #pragma unroll
        for (int nt = 0; nt < 4; nt++) {
            int col = wn + nt*8 + lt*2;
            float b0 = biass[col], b1 = biass[col+1];
            #pragma unroll
            for (int half = 0; half < 2; half++) {
                int r = row0 + wm + mt*16 + lg + half*8;
                if (r >= N) continue;
                float2 o;
                o.x = acc[mt][nt][half*2 + 0] + b0;
                o.y = acc[mt][nt][half*2 + 1] + b1;
                if (blend) {
                    float2 old = *(const float2*)&Cold[(size_t)r*HDIM + col];
                    o.x = fmaxf(askip*o.x + (1.f-askip)*old.x, 0.f);
                    o.y = fmaxf(askip*o.y + (1.f-askip)*old.y, 0.f);
                }
                *(float2*)&C[(size_t)r*HDIM + col] = o;
            }
        }
    }
}

// ---------------- multi-output tf32 GEMM: A staged once, NC weight chunks ----------------
struct MultiOut {
    float* ptr[5];
    int    stride[5];
};

template<int NC>
__global__ __launch_bounds__(256) void mma_gemm_multi(
        const float* __restrict__ A, const float* __restrict__ PW,
        const float* __restrict__ PB, MultiOut mo, int N)
{
    constexpr int KP = HDIM + 4;
    extern __shared__ uint32_t smu[];
    uint32_t* As = smu;            // 128 * KP
    uint32_t* Bs = smu + 128*KP;   // 128 * 132

    int tid = threadIdx.x;
    int row0 = blockIdx.x * 128;

    // stage A tile once
    for (int i = tid; i < 128*32; i += 256) {
        int r = i >> 5, c4 = i & 31;
        int n = row0 + r;
        float4 v = make_float4(0.f, 0.f, 0.f, 0.f);
        if (n < N) v = ((const float4*)A)[(size_t)n*32 + c4];
        uint32_t* dst = &As[r*KP + c4*4];
        dst[0] = f2tf32(v.x); dst[1] = f2tf32(v.y);
        dst[2] = f2tf32(v.z); dst[3] = f2tf32(v.w);
    }

    int lane = tid & 31, w = tid >> 5;
    int wm = (w & 1) * 64;
    int wn = (w >> 1) * 32;
    int lg = lane >> 2;
    int lt = lane & 3;

    #pragma unroll
    for (int c = 0; c < NC; c++) {
        __syncthreads();   // As ready / previous chunk's Bs reads done
        const float4* B4 = (const float4*)(PW + (size_t)c * HDIM * HDIM);
        for (int i = tid; i < 128*32; i += 256) {
            int k = i >> 5, c4 = i & 31;
            float4 v = B4[i];
            uint32_t* dst = &Bs[k*132 + c4*4];
            dst[0] = f2tf32(v.x); dst[1] = f2tf32(v.y);
            dst[2] = f2tf32(v.z); dst[3] = f2tf32(v.w);
        }
        __syncthreads();

        float acc[4][4][4];
        #pragma unroll
        for (int mt = 0; mt < 4; mt++)
            #pragma unroll
            for (int nt = 0; nt < 4; nt++)
                #pragma unroll
                for (int j = 0; j < 4; j++) acc[mt][nt][j] = 0.f;

        #pragma unroll 2
        for (int k0 = 0; k0 < HDIM; k0 += 8) {
            uint32_t af[4][4];
            #pragma unroll
            for (int mt = 0; mt < 4; mt++) {
                int r = wm + mt*16 + lg;
                af[mt][0] = As[r*KP + k0 + lt];
                af[mt][1] = As[(r+8)*KP + k0 + lt];
                af[mt][2] = As[r*KP + k0 + lt + 4];
                af[mt][3] = As[(r+8)*KP + k0 + lt + 4];
            }
            uint32_t bf[4][2];
            #pragma unroll
            for (int nt = 0; nt < 4; nt++) {
                bf[nt][0] = Bs[(k0 + lt)*132 + wn + nt*8 + lg];
                bf[nt][1] = Bs[(k0 + lt + 4)*132 + wn + nt*8 + lg];
            }
            #pragma unroll
            for (int mt = 0; mt < 4; mt++)
                #pragma unroll
                for (int nt = 0; nt < 4; nt++)
                    mma_tf32(acc[mt][nt], af[mt], bf[nt]);
        }

        float* out = mo.ptr[c];
        int st = mo.stride[c];
        const float* bb = PB + (size_t)c * HDIM;
        #pragma unroll
        for (int mt = 0; mt < 4; mt++) {
            #pragma unroll
            for (int nt = 0; nt < 4; nt++) {
                int col = wn + nt*8 + lt*2;
                float b0 = bb[col], b1 = bb[col+1];
                #pragma unroll
                for (int half = 0; half < 2; half++) {
                    int r = row0 + wm + mt*16 + lg + half*8;
                    if (r >= N) continue;
                    float2 o;
                    o.x = acc[mt][nt][half*2 + 0] + b0;
                    o.y = acc[mt][nt][half*2 + 1] + b1;
                    *(float2*)&out[(size_t)r*st + col] = o;
                }
            }
        }
    }
}

// ---------------- per-layer init: den=0, msg=0 ----------------
// msg buffers are N*HDIM floats = N*32 float4 each; den is N*NHEAD floats.
__global__ void fill_kernel(float* __restrict__ den0, float* __restrict__ den1,
                            float* __restrict__ msg0, float* __restrict__ msg1, int N)
{
    int i = blockIdx.x * blockDim.x + threadIdx.x;
    float4 z = make_float4(0.f, 0.f, 0.f, 0.f);
    if (i < N*32) {
        ((float4*)msg0)[i] = z;
        ((float4*)msg1)[i] = z;
    }
    if (i < N*NHEAD) {
        den0[i] = 0.f; den1[i] = 0.f;
    }
}

// ---------------- fused edge pass: score, exp, denominator + value scatter ----------------
__global__ void edge_fused_kernel(const int* __restrict__ edge, int E,
                                  const float* __restrict__ q,
                                  const float* __restrict__ ktvt,
                                  float* __restrict__ den, float* __restrict__ msg,
                                  const float* __restrict__ prel)
{
    int g = blockIdx.x * blockDim.x + threadIdx.x;
    int w = g >> 5;
    if (w >= E) return;
    int lane = threadIdx.x & 31;
    int src = __ldg(&edge[w]), dst = __ldg(&edge[E + w]);
    int h = lane >> 3, sub = lane & 7;

    const float4 qv = *(const float4*)&q[(size_t)dst*HDIM + h*DHEAD + sub*4];
    const float4 kv = *(const float4*)&ktvt[(size_t)src*256 + h*DHEAD + sub*4];
    float s = qv.x*kv.x + qv.y*kv.y + qv.z*kv.z + qv.w*kv.w;
    s += __shfl_xor_sync(0xffffffffu, s, 1);
    s += __shfl_xor_sync(0xffffffffu, s, 2);
    s += __shfl_xor_sync(0xffffffffu, s, 4);
    float e = expf(s * (__ldg(&prel[h]) * INV_SQRT_D));

    if (sub == 0) atomicAdd(&den[(size_t)dst*NHEAD + h], e);

    const float4 v = *(const float4*)&ktvt[(size_t)src*256 + 128 + h*DHEAD + sub*4];
    float* mp = &msg[(size_t)dst*HDIM + h*DHEAD + sub*4];
    asm volatile("red.global.add.v4.f32 [%0], {%1,%2,%3,%4};"
                 :: "l"(mp), "f"(e*v.x), "f"(e*v.y), "f"(e*v.z), "f"(e*v.w)
                 : "memory");
}

// ---------------- host orchestration ----------------
extern "C" void kernel_launch(void* const* d_in, const int* in_sizes, int n_in,
                              void* d_out, int out_size)
{
    const float* x_region = (const float*)d_in[0];
    const float* x_site   = (const float*)d_in[1];
    const float* pWr = (const float*)d_in[2];
    const float* pbr = (const float*)d_in[3];
    const float* pWs = (const float*)d_in[4];
    const float* pbs = (const float*)d_in[5];
    const float* Wk  = (const float*)d_in[6];
    const float* bk  = (const float*)d_in[7];
    const float* Wq  = (const float*)d_in[8];
    const float* bq  = (const float*)d_in[9];
    const float* Wv  = (const float*)d_in[10];
    const float* bv  = (const float*)d_in[11];
    const float* Wo  = (const float*)d_in[12];
    const float* bo  = (const float*)d_in[13];
    const float* skip = (const float*)d_in[14];
    const float* Krel = (const float*)d_in[15];
    const float* Vrel = (const float*)d_in[16];
    const float* prel = (const float*)d_in[17];
    const int* edges[3] = { (const int*)d_in[18], (const int*)d_in[19], (const int*)d_in[20] };

    int N = in_sizes[0] / 64;
    int E = in_sizes[18] / 2;

    float* base = nullptr;
    cudaGetSymbolAddress((void**)&base, g_scratch);

    float* xs[2]  = { base + O_XS0,  base + O_XS1 };
    float* qb[2]  = { base + O_Q0,   base + O_Q1 };
    float* ktvt[3] = { base + O_KTVT0, base + O_KTVT1, base + O_KTVT2 };
    float* msg[2] = { base + O_MSG0, base + O_MSG1 };
    float* den[2] = { base + O_DEN0, base + O_DEN1 };
    float* PW = base + O_PW;
    float* PB = base + O_PB;

    // dynamic smem sizes (bytes)
    const int SM128 = (128*132 + 128*132 + 128) * 4;
    const int SM64  = (128*68  + 64*132  + 128) * 4;
    const int SM32  = (128*36  + 32*132  + 128) * 4;
    const int SMM   = (128*132 + 128*132) * 4;
    cudaFuncSetAttribute(mma_gemm<128>, cudaFuncAttributeMaxDynamicSharedMemorySize, SM128);
    cudaFuncSetAttribute(mma_gemm<64>,  cudaFuncAttributeMaxDynamicSharedMemorySize, SM64);
    cudaFuncSetAttribute(mma_gemm<32>,  cudaFuncAttributeMaxDynamicSharedMemorySize, SM32);
    cudaFuncSetAttribute(mma_gemm_multi<3>, cudaFuncAttributeMaxDynamicSharedMemorySize, SMM);
    cudaFuncSetAttribute(mma_gemm_multi<5>, cudaFuncAttributeMaxDynamicSharedMemorySize, SMM);

    int gemmGrid = (N + 127) / 128;
    int edgeGrid = (E*32 + 255) / 256;
    int fillGrid = (N*32 + 255) / 256;

    // 0) packed weight chunks (16 chunks of 128x128)
    pack_kernel<<<16, 256>>>(Wq, bq, Wk, bk, Wv, bv, Krel, Vrel, PW, PB);

    // 1) input projections
    mma_gemm<64><<<gemmGrid, 256, SM64>>>(x_region, pWr, pbr, xs[0], nullptr, nullptr, nullptr, N, 0);
    mma_gemm<32><<<gemmGrid, 256, SM32>>>(x_site,   pWs, pbs, xs[1], nullptr, nullptr, nullptr, N, 0);

    const int L = 2;
    for (int l = 0; l < L; l++) {
        fill_kernel<<<fillGrid, 256>>>(den[0], den[1], msg[0], msg[1], N);

        // type 0: q + ktvt for edge type 0  (chunks 0..2)
        {
            MultiOut mo;
            mo.ptr[0] = qb[0];          mo.stride[0] = 128;
            mo.ptr[1] = ktvt[0];        mo.stride[1] = 256;
            mo.ptr[2] = ktvt[0] + 128;  mo.stride[2] = 256;
            mo.ptr[3] = nullptr; mo.ptr[4] = nullptr;
            mo.stride[3] = 0; mo.stride[4] = 0;
            mma_gemm_multi<3><<<gemmGrid, 256, SMM>>>(xs[0], PW + (size_t)(l*8+0)*HDIM*HDIM,
                                                      PB + (size_t)(l*8+0)*HDIM, mo, N);
        }
        // type 1: q + ktvt for edge types 1,2  (chunks 3..7)
        {
            MultiOut mo;
            mo.ptr[0] = qb[1];          mo.stride[0] = 128;
            mo.ptr[1] = ktvt[1];        mo.stride[1] = 256;
            mo.ptr[2] = ktvt[1] + 128;  mo.stride[2] = 256;
            mo.ptr[3] = ktvt[2];        mo.stride[3] = 256;
            mo.ptr[4] = ktvt[2] + 128;  mo.stride[4] = 256;
            mma_gemm_multi<5><<<gemmGrid, 256, SMM>>>(xs[1], PW + (size_t)(l*8+3)*HDIM*HDIM,
                                                      PB + (size_t)(l*8+3)*HDIM, mo, N);
        }

        // fused edge pass (ET = [(0,1),(1,0),(1,1)])
        edge_fused_kernel<<<edgeGrid, 256>>>(edges[0], E, qb[1], ktvt[0], den[1], msg[1],
                                             prel + (size_t)(l*3+0)*NHEAD);
        edge_fused_kernel<<<edgeGrid, 256>>>(edges[1], E, qb[0], ktvt[1], den[0], msg[0],
                                             prel + (size_t)(l*3+1)*NHEAD);
        edge_fused_kernel<<<edgeGrid, 256>>>(edges[2], E, qb[1], ktvt[2], den[1], msg[1],
                                             prel + (size_t)(l*3+2)*NHEAD);

        // finalize: out = relu(a*(gelu(msg/den)@Wo + bo) + (1-a)*xs)
        for (int t = 0; t < 2; t++) {
            float* Cptr = (l == L-1) ? ((float*)d_out + (size_t)t*N*HDIM) : xs[t];
            mma_gemm<128><<<gemmGrid, 256, SM128>>>(msg[t], Wo + (size_t)(l*2+t)*HDIM*HDIM,
                                                    bo + (size_t)(l*2+t)*HDIM, Cptr,
                                                    xs[t], den[t], skip + l*2 + t, N, 3);
        }
    }
}

// round 10
// speedup vs baseline: 2.0080x; 1.0510x over previous
#include <cuda_runtime.h>
#include <cuda_fp16.h>
#include <math.h>
#include <stdint.h>

// Problem constants (fixed shapes for this problem)
#define HN 100000      // nodes per type
#define EN 200000      // edges per edge type
#define HDIM 128       // hidden
#define NHEAD 4
#define DHEAD 32

static const float INV_SQRT_D = 0.17677669529663687f; // 1/sqrt(32)

// ---------------- scratch layout ----------------
constexpr size_t SN = (size_t)HN * HDIM;     // one [N,128] fp32 buffer
constexpr size_t O_XS0   = 0;
constexpr size_t O_XS1   = SN;
constexpr size_t O_Q0    = 2*SN;             // fp16 [N,128] (uses half the space)
constexpr size_t O_Q1    = 3*SN;
constexpr size_t O_KTVT0 = 4*SN;             // fp16 [N,256] kt|vt per edge type
constexpr size_t O_KTVT1 = 6*SN;
constexpr size_t O_KTVT2 = 8*SN;
constexpr size_t O_MSG0  = 10*SN;
constexpr size_t O_MSG1  = 11*SN;
constexpr size_t O_DEN0  = 12*SN;
constexpr size_t O_DEN1  = O_DEN0 + (size_t)HN*NHEAD;
constexpr size_t O_PW    = O_DEN1 + (size_t)HN*NHEAD;   // 16 chunks of 128*128
constexpr size_t O_PB    = O_PW + (size_t)16*HDIM*HDIM; // 16 * 128
constexpr size_t SCRATCH_TOTAL = O_PB + (size_t)16*HDIM;

__device__ float g_scratch[SCRATCH_TOTAL];

// ---------------- helpers ----------------
__device__ __forceinline__ float gelu_exact(float x) {
    return 0.5f * x * (1.0f + erff(x * 0.70710678118654752f));
}

__device__ __forceinline__ uint32_t f2tf32(float x) {
    uint32_t u;
    asm("cvt.rna.tf32.f32 %0, %1;" : "=r"(u) : "f"(x));
    return u;
}

__device__ __forceinline__ void mma_tf32(float c[4], const uint32_t a[4], const uint32_t b[2]) {
    asm volatile(
        "mma.sync.aligned.m16n8k8.row.col.f32.tf32.tf32.f32 "
        "{%0,%1,%2,%3}, {%4,%5,%6,%7}, {%8,%9}, {%0,%1,%2,%3};"
        : "+f"(c[0]), "+f"(c[1]), "+f"(c[2]), "+f"(c[3])
        : "r"(a[0]), "r"(a[1]), "r"(a[2]), "r"(a[3]), "r"(b[0]), "r"(b[1]));
}

// ---------------- pack kernel: packed weight chunks per (layer, node type) ----------------
// Chunk map per layer (8 chunks of 128x128):
//   c0: Wq[l][0]                   (type 0)
//   c1: Wk[l][0] o Krel[l][0]      (type 0, edge r0: src=0)
//   c2: Wv[l][0] o Vrel[l][0]
//   c3: Wq[l][1]                   (type 1)
//   c4: Wk[l][1] o Krel[l][1]      (edge r1: src=1)
//   c5: Wv[l][1] o Vrel[l][1]
//   c6: Wk[l][1] o Krel[l][2]      (edge r2: src=1)
//   c7: Wv[l][1] o Vrel[l][2]
__global__ void pack_kernel(const float* __restrict__ Wq, const float* __restrict__ bq,
                            const float* __restrict__ Wk, const float* __restrict__ bk,
                            const float* __restrict__ Wv, const float* __restrict__ bv,
                            const float* __restrict__ Krel, const float* __restrict__ Vrel,
                            float* __restrict__ PW, float* __restrict__ PB)
{
    int b = blockIdx.x;     // 0..15
    int l = b >> 3, c = b & 7;
    float* WO = PW + (size_t)b * HDIM * HDIM;
    float* bO = PB + (size_t)b * HDIM;

    if (c == 0 || c == 3) {
        int t = (c == 3);
        const float* W = Wq + (size_t)(l*2 + t) * HDIM * HDIM;
        const float* bb = bq + (size_t)(l*2 + t) * HDIM;
        for (int i = threadIdx.x; i < HDIM*HDIM; i += blockDim.x) WO[i] = W[i];
        if (threadIdx.x < HDIM) bO[threadIdx.x] = bb[threadIdx.x];
        return;
    }

    int kv, r, s;
    if (c == 1) { kv = 0; r = 0; s = 0; }
    else if (c == 2) { kv = 1; r = 0; s = 0; }
    else if (c == 4) { kv = 0; r = 1; s = 1; }
    else if (c == 5) { kv = 1; r = 1; s = 1; }
    else if (c == 6) { kv = 0; r = 2; s = 1; }
    else { kv = 1; r = 2; s = 1; }

    const float* W  = (kv ? Wv : Wk) + (size_t)(l*2 + s) * HDIM * HDIM;
    const float* bb = (kv ? bv : bk) + (size_t)(l*2 + s) * HDIM;
    const float* R  = (kv ? Vrel : Krel) + (size_t)(l*3 + r) * NHEAD * DHEAD * DHEAD;

    __shared__ float Rs[NHEAD*DHEAD*DHEAD];
    for (int i = threadIdx.x; i < NHEAD*DHEAD*DHEAD; i += blockDim.x) Rs[i] = R[i];
    __syncthreads();

    for (int o = threadIdx.x; o < HDIM*HDIM; o += blockDim.x) {
        int i = o >> 7, j = o & 127;
        int h = j >> 5, e = j & 31;
        float sum = 0.f;
        #pragma unroll
        for (int d = 0; d < DHEAD; d++)
            sum += W[i*HDIM + h*DHEAD + d] * Rs[(h*DHEAD + d)*DHEAD + e];
        WO[o] = sum;
    }
    if (threadIdx.x < HDIM) {
        int j = threadIdx.x, h = j >> 5, e = j & 31;
        float sum = 0.f;
        #pragma unroll
        for (int d = 0; d < DHEAD; d++)
            sum += bb[h*DHEAD + d] * Rs[(h*DHEAD + d)*DHEAD + e];
        bO[j] = sum;
    }
}

// ---------------- single-output tf32 GEMM, fp32 out (input proj + finalize) ----------------
// flags bit0: pre-gelu (A = gelu(A/den)), bit1: post skip-blend + relu (reads Cold)
template<int K>
__global__ __launch_bounds__(256) void mma_gemm(
        const float* __restrict__ A, const float* __restrict__ B,
        const float* __restrict__ bias, float* __restrict__ C,
        const float* __restrict__ Cold, const float* __restrict__ den,
        const float* __restrict__ skipPtr, int N, int flags)
{
    constexpr int KP = K + 4;
    constexpr int K4 = K / 4;
    extern __shared__ uint32_t smu[];
    uint32_t* As = smu;                  // 128 * KP
    uint32_t* Bs = smu + 128*KP;         // K * 132
    float* biass = (float*)(Bs + K*132); // 128

    int tid = threadIdx.x;
    int row0 = blockIdx.x * 128;
    bool preGelu = flags & 1;

    if (tid < 128) biass[tid] = bias[tid];

    const float4* B4 = (const float4*)B;
    for (int i = tid; i < K*32; i += 256) {
        int k = i >> 5, c4 = i & 31;
        float4 v = B4[i];
        uint32_t* dst = &Bs[k*132 + c4*4];
        dst[0] = f2tf32(v.x); dst[1] = f2tf32(v.y);
        dst[2] = f2tf32(v.z); dst[3] = f2tf32(v.w);
    }

    for (int i = tid; i < 128*K4; i += 256) {
        int r = i / K4, c4 = i % K4;
        int n = row0 + r;
        float4 v = make_float4(0.f, 0.f, 0.f, 0.f);
        if (n < N) {
            v = ((const float4*)A)[(size_t)n*K4 + c4];
            if (preGelu) {
                float d = den[(size_t)n*NHEAD + (c4 >> 3)];
                float inv = (d > 0.f) ? 1.f/d : 0.f;
                v.x = gelu_exact(v.x*inv); v.y = gelu_exact(v.y*inv);
                v.z = gelu_exact(v.z*inv); v.w = gelu_exact(v.w*inv);
            }
        }
        uint32_t* dst = &As[r*KP + c4*4];
        dst[0] = f2tf32(v.x); dst[1] = f2tf32(v.y);
        dst[2] = f2tf32(v.z); dst[3] = f2tf32(v.w);
    }
    __syncthreads();

    int lane = tid & 31, w = tid >> 5;
    int wm = (w & 1) * 64;
    int wn = (w >> 1) * 32;
    int lg = lane >> 2;
    int lt = lane & 3;

    float acc[4][4][4];
    #pragma unroll
    for (int mt = 0; mt < 4; mt++)
        #pragma unroll
        for (int nt = 0; nt < 4; nt++)
            #pragma unroll
            for (int j = 0; j < 4; j++) acc[mt][nt][j] = 0.f;

    #pragma unroll 2
    for (int k0 = 0; k0 < K; k0 += 8) {
        uint32_t af[4][4];
        #pragma unroll
        for (int mt = 0; mt < 4; mt++) {
            int r = wm + mt*16 + lg;
            af[mt][0] = As[r*KP + k0 + lt];
            af[mt][1] = As[(r+8)*KP + k0 + lt];
            af[mt][2] = As[r*KP + k0 + lt + 4];
            af[mt][3] = As[(r+8)*KP + k0 + lt + 4];
        }
        uint32_t bf[4][2];
        #pragma unroll
        for (int nt = 0; nt < 4; nt++) {
            bf[nt][0] = Bs[(k0 + lt)*132 + wn + nt*8 + lg];
            bf[nt][1] = Bs[(k0 + lt + 4)*132 + wn + nt*8 + lg];
        }
        #pragma unroll
        for (int mt = 0; mt < 4; mt++)
            #pragma unroll
            for (int nt = 0; nt < 4; nt++)
                mma_tf32(acc[mt][nt], af[mt], bf[nt]);
    }

    bool blend = flags & 2;
    float askip = 0.f;
    if (blend) askip = 1.f / (1.f + expf(-skipPtr[0]));

    #pragma unroll
    for (int mt = 0; mt < 4; mt++) {
        #pragma unroll
        for (int nt = 0; nt < 4; nt++) {
            int col = wn + nt*8 + lt*2;
            float b0 = biass[col], b1 = biass[col+1];
            #pragma unroll
            for (int half = 0; half < 2; half++) {
                int r = row0 + wm + mt*16 + lg + half*8;
                if (r >= N) continue;
                float2 o;
                o.x = acc[mt][nt][half*2 + 0] + b0;
                o.y = acc[mt][nt][half*2 + 1] + b1;
                if (blend) {
                    float2 old = *(const float2*)&Cold[(size_t)r*HDIM + col];
                    o.x = fmaxf(askip*o.x + (1.f-askip)*old.x, 0.f);
                    o.y = fmaxf(askip*o.y + (1.f-askip)*old.y, 0.f);
                }
                *(float2*)&C[(size_t)r*HDIM + col] = o;
            }
        }
    }
}

// ---------------- multi-output tf32 GEMM: A staged once, NC chunks, FP16 outputs ----------------
struct MultiOut {
    __half* ptr[5];
    int     stride[5];   // in half elements
};

template<int NC>
__global__ __launch_bounds__(256) void mma_gemm_multi(
        const float* __restrict__ A, const float* __restrict__ PW,
        const float* __restrict__ PB, MultiOut mo, int N)
{
    constexpr int KP = HDIM + 4;
    extern __shared__ uint32_t smu[];
    uint32_t* As = smu;            // 128 * KP
    uint32_t* Bs = smu + 128*KP;   // 128 * 132

    int tid = threadIdx.x;
    int row0 = blockIdx.x * 128;

    // stage A tile once
    for (int i = tid; i < 128*32; i += 256) {
        int r = i >> 5, c4 = i & 31;
        int n = row0 + r;
        float4 v = make_float4(0.f, 0.f, 0.f, 0.f);
        if (n < N) v = ((const float4*)A)[(size_t)n*32 + c4];
        uint32_t* dst = &As[r*KP + c4*4];
        dst[0] = f2tf32(v.x); dst[1] = f2tf32(v.y);
        dst[2] = f2tf32(v.z); dst[3] = f2tf32(v.w);
    }

    int lane = tid & 31, w = tid >> 5;
    int wm = (w & 1) * 64;
    int wn = (w >> 1) * 32;
    int lg = lane >> 2;
    int lt = lane & 3;

    #pragma unroll
    for (int c = 0; c < NC; c++) {
        __syncthreads();   // As ready / previous chunk's Bs reads done
        const float4* B4 = (const float4*)(PW + (size_t)c * HDIM * HDIM);
        for (int i = tid; i < 128*32; i += 256) {
            int k = i >> 5, c4 = i & 31;
            float4 v = B4[i];
            uint32_t* dst = &Bs[k*132 + c4*4];
            dst[0] = f2tf32(v.x); dst[1] = f2tf32(v.y);
            dst[2] = f2tf32(v.z); dst[3] = f2tf32(v.w);
        }
        __syncthreads();

        float acc[4][4][4];
        #pragma unroll
        for (int mt = 0; mt < 4; mt++)
            #pragma unroll
            for (int nt = 0; nt < 4; nt++)
                #pragma unroll
                for (int j = 0; j < 4; j++) acc[mt][nt][j] = 0.f;

        #pragma unroll 2
        for (int k0 = 0; k0 < HDIM; k0 += 8) {
            uint32_t af[4][4];
            #pragma unroll
            for (int mt = 0; mt < 4; mt++) {
                int r = wm + mt*16 + lg;
                af[mt][0] = As[r*KP + k0 + lt];
                af[mt][1] = As[(r+8)*KP + k0 + lt];
                af[mt][2] = As[r*KP + k0 + lt + 4];
                af[mt][3] = As[(r+8)*KP + k0 + lt + 4];
            }
            uint32_t bf[4][2];
            #pragma unroll
            for (int nt = 0; nt < 4; nt++) {
                bf[nt][0] = Bs[(k0 + lt)*132 + wn + nt*8 + lg];
                bf[nt][1] = Bs[(k0 + lt + 4)*132 + wn + nt*8 + lg];
            }
            #pragma unroll
            for (int mt = 0; mt < 4; mt++)
                #pragma unroll
                for (int nt = 0; nt < 4; nt++)
                    mma_tf32(acc[mt][nt], af[mt], bf[nt]);
        }

        __half* out = mo.ptr[c];
        int st = mo.stride[c];
        const float* bb = PB + (size_t)c * HDIM;
        #pragma unroll
        for (int mt = 0; mt < 4; mt++) {
            #pragma unroll
            for (int nt = 0; nt < 4; nt++) {
                int col = wn + nt*8 + lt*2;
                float b0 = bb[col], b1 = bb[col+1];
                #pragma unroll
                for (int half = 0; half < 2; half++) {
                    int r = row0 + wm + mt*16 + lg + half*8;
                    if (r >= N) continue;
                    __half2 hv = __floats2half2_rn(acc[mt][nt][half*2 + 0] + b0,
                                                   acc[mt][nt][half*2 + 1] + b1);
                    *(__half2*)&out[(size_t)r*st + col] = hv;
                }
            }
        }
    }
}

// ---------------- per-layer init: den=0, msg=0 ----------------
__global__ void fill_kernel(float* __restrict__ den0, float* __restrict__ den1,
                            float* __restrict__ msg0, float* __restrict__ msg1, int N)
{
    int i = blockIdx.x * blockDim.x + threadIdx.x;
    float4 z = make_float4(0.f, 0.f, 0.f, 0.f);
    if (i < N*32) {
        ((float4*)msg0)[i] = z;
        ((float4*)msg1)[i] = z;
    }
    if (i < N*NHEAD) {
        den0[i] = 0.f; den1[i] = 0.f;
    }
}

// ---------------- fused edge pass (fp16 q/ktvt, fp32 math + scatter) ----------------
__global__ void edge_fused_kernel(const int* __restrict__ edge, int E,
                                  const __half* __restrict__ q,
                                  const __half* __restrict__ ktvt,
                                  float* __restrict__ den, float* __restrict__ msg,
                                  const float* __restrict__ prel)
{
    int g = blockIdx.x * blockDim.x + threadIdx.x;
    int w = g >> 5;
    if (w >= E) return;
    int lane = threadIdx.x & 31;
    int src = __ldg(&edge[w]), dst = __ldg(&edge[E + w]);
    int h = lane >> 3, sub = lane & 7;

    // 4 halfs each (8 bytes) — full warp covers the 128-half row
    const __half2* qp = (const __half2*)&q[(size_t)dst*HDIM + h*DHEAD + sub*4];
    const __half2* kp = (const __half2*)&ktvt[(size_t)src*256 + h*DHEAD + sub*4];
    float2 q0 = __half22float2(qp[0]), q1 = __half22float2(qp[1]);
    float2 k0 = __half22float2(kp[0]), k1 = __half22float2(kp[1]);
    float s = q0.x*k0.x + q0.y*k0.y + q1.x*k1.x + q1.y*k1.y;
    s += __shfl_xor_sync(0xffffffffu, s, 1);
    s += __shfl_xor_sync(0xffffffffu, s, 2);
    s += __shfl_xor_sync(0xffffffffu, s, 4);
    float e = expf(s * (__ldg(&prel[h]) * INV_SQRT_D));

    if (sub == 0) atomicAdd(&den[(size_t)dst*NHEAD + h], e);

    const __half2* vp = (const __half2*)&ktvt[(size_t)src*256 + 128 + h*DHEAD + sub*4];
    float2 v0 = __half22float2(vp[0]), v1 = __half22float2(vp[1]);
    float* mp = &msg[(size_t)dst*HDIM + h*DHEAD + sub*4];
    asm volatile("red.global.add.v4.f32 [%0], {%1,%2,%3,%4};"
                 :: "l"(mp), "f"(e*v0.x), "f"(e*v0.y), "f"(e*v1.x), "f"(e*v1.y)
                 : "memory");
}

// ---------------- host orchestration ----------------
extern "C" void kernel_launch(void* const* d_in, const int* in_sizes, int n_in,
                              void* d_out, int out_size)
{
    const float* x_region = (const float*)d_in[0];
    const float* x_site   = (const float*)d_in[1];
    const float* pWr = (const float*)d_in[2];
    const float* pbr = (const float*)d_in[3];
    const float* pWs = (const float*)d_in[4];
    const float* pbs = (const float*)d_in[5];
    const float* Wk  = (const float*)d_in[6];
    const float* bk  = (const float*)d_in[7];
    const float* Wq  = (const float*)d_in[8];
    const float* bq  = (const float*)d_in[9];
    const float* Wv  = (const float*)d_in[10];
    const float* bv  = (const float*)d_in[11];
    const float* Wo  = (const float*)d_in[12];
    const float* bo  = (const float*)d_in[13];
    const float* skip = (const float*)d_in[14];
    const float* Krel = (const float*)d_in[15];
    const float* Vrel = (const float*)d_in[16];
    const float* prel = (const float*)d_in[17];
    const int* edges[3] = { (const int*)d_in[18], (const int*)d_in[19], (const int*)d_in[20] };

    int N = in_sizes[0] / 64;
    int E = in_sizes[18] / 2;

    float* base = nullptr;
    cudaGetSymbolAddress((void**)&base, g_scratch);

    float* xs[2]   = { base + O_XS0,  base + O_XS1 };
    __half* qb[2]  = { (__half*)(base + O_Q0), (__half*)(base + O_Q1) };
    __half* ktvt[3] = { (__half*)(base + O_KTVT0), (__half*)(base + O_KTVT1), (__half*)(base + O_KTVT2) };
    float* msg[2] = { base + O_MSG0, base + O_MSG1 };
    float* den[2] = { base + O_DEN0, base + O_DEN1 };
    float* PW = base + O_PW;
    float* PB = base + O_PB;

    // dynamic smem sizes (bytes)
    const int SM128 = (128*132 + 128*132 + 128) * 4;
    const int SM64  = (128*68  + 64*132  + 128) * 4;
    const int SM32  = (128*36  + 32*132  + 128) * 4;
    const int SMM   = (128*132 + 128*132) * 4;
    cudaFuncSetAttribute(mma_gemm<128>, cudaFuncAttributeMaxDynamicSharedMemorySize, SM128);
    cudaFuncSetAttribute(mma_gemm<64>,  cudaFuncAttributeMaxDynamicSharedMemorySize, SM64);
    cudaFuncSetAttribute(mma_gemm<32>,  cudaFuncAttributeMaxDynamicSharedMemorySize, SM32);
    cudaFuncSetAttribute(mma_gemm_multi<3>, cudaFuncAttributeMaxDynamicSharedMemorySize, SMM);
    cudaFuncSetAttribute(mma_gemm_multi<5>, cudaFuncAttributeMaxDynamicSharedMemorySize, SMM);

    int gemmGrid = (N + 127) / 128;
    int edgeGrid = (E*32 + 255) / 256;
    int fillGrid = (N*32 + 255) / 256;

    // 0) packed weight chunks (16 chunks of 128x128)
    pack_kernel<<<16, 256>>>(Wq, bq, Wk, bk, Wv, bv, Krel, Vrel, PW, PB);

    // 1) input projections
    mma_gemm<64><<<gemmGrid, 256, SM64>>>(x_region, pWr, pbr, xs[0], nullptr, nullptr, nullptr, N, 0);
    mma_gemm<32><<<gemmGrid, 256, SM32>>>(x_site,   pWs, pbs, xs[1], nullptr, nullptr, nullptr, N, 0);

    const int L = 2;
    for (int l = 0; l < L; l++) {
        fill_kernel<<<fillGrid, 256>>>(den[0], den[1], msg[0], msg[1], N);

        // type 0: q + ktvt for edge type 0  (chunks 0..2)
        {
            MultiOut mo;
            mo.ptr[0] = qb[0];          mo.stride[0] = 128;
            mo.ptr[1] = ktvt[0];        mo.stride[1] = 256;
            mo.ptr[2] = ktvt[0] + 128;  mo.stride[2] = 256;
            mo.ptr[3] = nullptr; mo.ptr[4] = nullptr;
            mo.stride[3] = 0; mo.stride[4] = 0;
            mma_gemm_multi<3><<<gemmGrid, 256, SMM>>>(xs[0], PW + (size_t)(l*8+0)*HDIM*HDIM,
                                                      PB + (size_t)(l*8+0)*HDIM, mo, N);
        }
        // type 1: q + ktvt for edge types 1,2  (chunks 3..7)
        {
            MultiOut mo;
            mo.ptr[0] = qb[1];          mo.stride[0] = 128;
            mo.ptr[1] = ktvt[1];        mo.stride[1] = 256;
            mo.ptr[2] = ktvt[1] + 128;  mo.stride[2] = 256;
            mo.ptr[3] = ktvt[2];        mo.stride[3] = 256;
            mo.ptr[4] = ktvt[2] + 128;  mo.stride[4] = 256;
            mma_gemm_multi<5><<<gemmGrid, 256, SMM>>>(xs[1], PW + (size_t)(l*8+3)*HDIM*HDIM,
                                                      PB + (size_t)(l*8+3)*HDIM, mo, N);
        }

        // fused edge pass (ET = [(0,1),(1,0),(1,1)])
        edge_fused_kernel<<<edgeGrid, 256>>>(edges[0], E, qb[1], ktvt[0], den[1], msg[1],
                                             prel + (size_t)(l*3+0)*NHEAD);
        edge_fused_kernel<<<edgeGrid, 256>>>(edges[1], E, qb[0], ktvt[1], den[0], msg[0],
                                             prel + (size_t)(l*3+1)*NHEAD);
        edge_fused_kernel<<<edgeGrid, 256>>>(edges[2], E, qb[1], ktvt[2], den[1], msg[1],
                                             prel + (size_t)(l*3+2)*NHEAD);

        // finalize: out = relu(a*(gelu(msg/den)@Wo + bo) + (1-a)*xs)
        for (int t = 0; t < 2; t++) {
            float* Cptr = (l == L-1) ? ((float*)d_out + (size_t)t*N*HDIM) : xs[t];
            mma_gemm<128><<<gemmGrid, 256, SM128>>>(msg[t], Wo + (size_t)(l*2+t)*HDIM*HDIM,
                                                    bo + (size_t)(l*2+t)*HDIM, Cptr,
                                                    xs[t], den[t], skip + l*2 + t, N, 3);
        }
    }
}